// round 14
// baseline (speedup 1.0000x reference)
#include <cuda_runtime.h>
#include <cuda_fp16.h>
#include <math.h>
#include <stdint.h>

// Problem constants
#define NN   30000
#define NE   60000
#define FEAT 256
#define HID  1024
#define OUTD 256
#define RANK 64
#define NC   1280   // HID + OUTD (merged G2+G4)

// ---------------- scratch (device globals) ----------------
__device__ __half g_embH    [NN * FEAT];
__device__ float  g_emb_new [NN * RANK];
__device__ __half g_hidden  [NN * HID];
__device__ __half g_emb_new2[NN * OUTD];
__device__ float  g_residual[NN * OUTD];
__device__ __half g_tee     [NE * 4 * RANK];
__device__ __half g_esum2   [NE * OUTD];
__device__ float  g_nodeacc [NN * OUTD];
__device__ __half g_accRh   [NN * RANK];
__device__ int    g_offs    [NN + 1];
__device__ int    g_cursor  [NN];
__device__ int    g_csr     [NE * 4];
// K-major fp16 weights
__device__ __half g_WtC [NC * FEAT];
__device__ __half g_Wt2 [OUTD * HID];
__device__ __half g_WtP [RANK * FEAT];
__device__ __half g_WtQ [OUTD * RANK];
__device__ float  g_biasC [NC];
__device__ float  g_biasP [RANK];

// ---------------- helpers ----------------
__device__ __forceinline__ uint32_t smem_u32(const void* p) {
    uint32_t a;
    asm("{ .reg .u64 t; cvta.to.shared.u64 t, %1; cvt.u32.u64 %0, t; }" : "=r"(a) : "l"(p));
    return a;
}
__device__ __forceinline__ uint32_t h2_as_u32(__half2 h) {
    uint32_t u;
    memcpy(&u, &h, 4);
    return u;
}
__device__ __forceinline__ void cp16(uint32_t dst, const void* src, int szbytes) {
    asm volatile("cp.async.ca.shared.global [%0], [%1], 16, %2;"
                 :: "r"(dst), "l"(src), "r"(szbytes) : "memory");
}
#define CP_COMMIT() asm volatile("cp.async.commit_group;" ::: "memory")
#define CP_WAIT(n)  asm volatile("cp.async.wait_group %0;" :: "n"(n) : "memory")

__device__ __forceinline__ void mma16n8k16(float* d, const uint32_t* a, const uint32_t* b) {
    asm volatile(
        "mma.sync.aligned.m16n8k16.row.col.f32.f16.f16.f32 "
        "{%0,%1,%2,%3}, {%4,%5,%6,%7}, {%8,%9}, {%0,%1,%2,%3};"
        : "+f"(d[0]), "+f"(d[1]), "+f"(d[2]), "+f"(d[3])
        : "r"(a[0]), "r"(a[1]), "r"(a[2]), "r"(a[3]), "r"(b[0]), "r"(b[1]));
}
__device__ __forceinline__ void ldsm_x4(uint32_t* r, uint32_t addr) {
    asm volatile("ldmatrix.sync.aligned.m8n8.x4.shared.b16 {%0,%1,%2,%3}, [%4];"
        : "=r"(r[0]), "=r"(r[1]), "=r"(r[2]), "=r"(r[3]) : "r"(addr));
}

// ---------------- mega-prep ----------------
__global__ void prep_all(const float* __restrict__ emb,
                         const float* __restrict__ p2W1, const float* __restrict__ p2W2,
                         const float* __restrict__ aW,   const float* __restrict__ pW,
                         const float* __restrict__ qW,
                         const float* __restrict__ p2b1, const float* __restrict__ ab_,
                         const float* __restrict__ pb_,  int n4)
{
    __shared__ float t[32][33];
    const int bx = blockIdx.x;
    const int tid = threadIdx.x;
    if (bx < 608) {
        const float* W; __half* Wt; int K, N, t0;
        if      (bx < 256) { W = p2W1; Wt = g_WtC;              K = FEAT; N = HID;  t0 = 0;   }
        else if (bx < 512) { W = p2W2; Wt = g_Wt2;              K = HID;  N = OUTD; t0 = 256; }
        else if (bx < 576) { W = aW;   Wt = g_WtC + HID * FEAT; K = FEAT; N = OUTD; t0 = 512; }
        else if (bx < 592) { W = pW;   Wt = g_WtP;              K = FEAT; N = RANK; t0 = 576; }
        else               { W = qW;   Wt = g_WtQ;              K = RANK; N = OUTD; t0 = 592; }
        int tt = bx - t0;
        int tiles_n = N >> 5;
        int n0 = (tt % tiles_n) * 32, k0 = (tt / tiles_n) * 32;
        int tx = tid & 31, ty = tid >> 5;
        for (int i = ty; i < 32; i += 8)
            t[i][tx] = W[(k0 + i) * N + n0 + tx];
        __syncthreads();
        for (int i = ty; i < 32; i += 8)
            Wt[(n0 + i) * K + k0 + tx] = __float2half_rn(t[tx][i]);
    } else if (bx < 614) {
        int i = (bx - 608) * 256 + tid;
        if      (i < HID)        g_biasC[i] = p2b1[i] + p2W1[FEAT * HID + i];
        else if (i < HID + OUTD) g_biasC[i] = ab_[i - HID] + aW[FEAT * OUTD + (i - HID)];
        else if (i < HID + OUTD + RANK) g_biasP[i - HID - OUTD] = pb_[i - HID - OUTD] + pW[FEAT * RANK + (i - HID - OUTD)];
    } else {
        int i = (bx - 614) * 256 + tid;
        if (i < n4) {
            float4 v = ((const float4*)emb)[i];
            uint2 o;
            o.x = h2_as_u32(__floats2half2_rn(v.x, v.y));
            o.y = h2_as_u32(__floats2half2_rn(v.z, v.w));
            ((uint2*)g_embH)[i] = o;
        }
    }
}

// ---------------- CSR offsets ----------------
__global__ __launch_bounds__(1024)
void scan_offsets(const int* __restrict__ deg, int* __restrict__ offs,
                  int* __restrict__ cursor, int N)
{
    constexpr int CE = 32;
    const int tid = threadIdx.x;
    const int start = tid * CE;

    int local = 0;
    if (start < N) {
        #pragma unroll
        for (int j = 0; j < CE; j += 4) {
            int i = start + j;
            if (i + 3 < N) {
                int4 v = *(const int4*)(deg + i);
                local += v.x + v.y + v.z + v.w;
            } else {
                #pragma unroll
                for (int k = 0; k < 4; k++) if (i + k < N) local += deg[i + k];
            }
        }
    }
    __shared__ int warpsum[32];
    int lane = tid & 31, w = tid >> 5;
    int x = local;
    #pragma unroll
    for (int o = 1; o < 32; o <<= 1) { int y = __shfl_up_sync(~0u, x, o); if (lane >= o) x += y; }
    if (lane == 31) warpsum[w] = x;
    __syncthreads();
    if (w == 0) {
        int s = warpsum[lane];
        #pragma unroll
        for (int o = 1; o < 32; o <<= 1) { int y = __shfl_up_sync(~0u, s, o); if (lane >= o) s += y; }
        warpsum[lane] = s;
    }
    __syncthreads();
    int base = x - local + (w > 0 ? warpsum[w - 1] : 0);

    if (start < N) {
        int run = base;
        #pragma unroll
        for (int j = 0; j < CE; j++) {
            int i = start + j;
            if (i < N) { offs[i] = run; cursor[i] = 0; run += deg[i]; }
        }
        if (tid == (N - 1) / CE) offs[N] = run;
    }
}

__global__ void csr_fill(const int* __restrict__ inc_node, const int* __restrict__ inc_edge,
                         const int* __restrict__ inc_slot, int NINC)
{
    int i = blockIdx.x * blockDim.x + threadIdx.x;
    if (i < NINC) {
        int n = inc_node[i];
        int p = atomicAdd(&g_cursor[n], 1);
        g_csr[g_offs[n] + p] = (inc_edge[i] << 2) | inc_slot[i];
    }
}

// ---------------- fp16 tensor-core GEMM (m16n8k16 + ldmatrix) ----------------
// mode 0: C(f32) = acc + bias
// mode 2: C(f32) = relu((acc + addSrc)/deg + bias) + resid
// mode 3: col<HID -> relu -> half2 (stride HID); else relu -> f32 C2 (stride OUTD)
// mode 4: C = half2(acc + bias), stride N (fp16 output, no relu)
template<int NT>
__global__ __launch_bounds__(256, 2)
void mma_gemm(const __half* __restrict__ A, const __half* __restrict__ Bt,
              const float* __restrict__ bias,
              float* __restrict__ C, float* __restrict__ C2,
              int M, int N, int K, int mode,
              const float* __restrict__ addSrc, const float* __restrict__ resid,
              const int* __restrict__ degv)
{
    constexpr int STW = 20;
    constexpr int NTILES = NT / 16;
    extern __shared__ uint32_t dyn32[];
    uint32_t* Asm = dyn32;
    uint32_t* Bsm = dyn32 + 2 * 128 * STW;

    const int tid  = threadIdx.x;
    const int wid  = tid >> 5;
    const int lane = tid & 31;
    const int grp  = lane >> 2;
    const int tig  = lane & 3;
    const int warpM = (wid & 3) * 32;
    const int warpN = (wid >> 2) * (NT / 2);
    const int rowBase = blockIdx.y * 128;
    const int colBase = blockIdx.x * NT;

    float acc[2][NTILES][4];
    #pragma unroll
    for (int mt = 0; mt < 2; mt++)
        #pragma unroll
        for (int nt = 0; nt < NTILES; nt++)
            #pragma unroll
            for (int i = 0; i < 4; i++) acc[mt][nt][i] = 0.f;

    const uint32_t asm_base = smem_u32(Asm);
    const uint32_t bsm_base = smem_u32(Bsm);

    const int lrow8 = lane & 7;
    const int a_row_off = lrow8 + (((lane >> 3) & 1) << 3);
    const int a_col_off = ((lane >> 4) << 2);
    const int b_row_off = lrow8 + ((lane >> 4) << 3);
    const int b_col_off = (((lane >> 3) & 1) << 2);

    auto loadChunk = [&](int c, int buf) {
        #pragma unroll
        for (int i = 0; i < 2; i++) {
            int idx = tid + (i << 8);
            int r = idx >> 2, seg = idx & 3;
            int gr = rowBase + r;
            const __half* src = A + (size_t)gr * K + (c << 5) + (seg << 3);
            uint32_t dst = asm_base + (buf * 128 * STW + r * STW + (seg << 2)) * 4;
            cp16(dst, src, gr < M ? 16 : 0);
        }
        #pragma unroll
        for (int i = 0; i < NT / 64; i++) {
            int idx = tid + (i << 8);
            int r = idx >> 2, seg = idx & 3;
            const __half* src = Bt + (size_t)(colBase + r) * K + (c << 5) + (seg << 3);
            uint32_t dst = bsm_base + (buf * NT * STW + r * STW + (seg << 2)) * 4;
            cp16(dst, src, 16);
        }
        CP_COMMIT();
    };

    const int nch = K >> 5;
    loadChunk(0, 0);

    for (int c = 0; c < nch; ++c) {
        const int buf = c & 1;
        if (c + 1 < nch) { loadChunk(c + 1, buf ^ 1); CP_WAIT(1); }
        else             { CP_WAIT(0); }
        __syncthreads();

        const uint32_t abase = asm_base + (buf * 128 * STW) * 4;
        const uint32_t bbase = bsm_base + (buf * NT * STW) * 4;
        #pragma unroll
        for (int ks = 0; ks < 2; ++ks) {
            const int kw = ks << 3;
            uint32_t afr[2][4];
            #pragma unroll
            for (int mt = 0; mt < 2; mt++) {
                uint32_t ad = abase +
                    ((warpM + mt * 16 + a_row_off) * STW + kw + a_col_off) * 4;
                ldsm_x4(afr[mt], ad);
            }
            uint32_t bfr[NTILES][2];
            #pragma unroll
            for (int p = 0; p < NTILES / 2; p++) {
                uint32_t bd = bbase +
                    ((warpN + p * 16 + b_row_off) * STW + kw + b_col_off) * 4;
                uint32_t r4[4];
                ldsm_x4(r4, bd);
                bfr[2 * p][0] = r4[0]; bfr[2 * p][1] = r4[1];
                bfr[2 * p + 1][0] = r4[2]; bfr[2 * p + 1][1] = r4[3];
            }
            #pragma unroll
            for (int mt = 0; mt < 2; mt++)
                #pragma unroll
                for (int nt = 0; nt < NTILES; nt++)
                    mma16n8k16(acc[mt][nt], afr[mt], bfr[nt]);
        }
        __syncthreads();
    }

    #pragma unroll
    for (int mt = 0; mt < 2; mt++) {
        #pragma unroll
        for (int nt = 0; nt < NTILES; nt++) {
            int col = colBase + warpN + nt * 8 + (tig << 1);
            float b0 = bias[col], b1 = bias[col + 1];
            #pragma unroll
            for (int h = 0; h < 2; h++) {
                int row = rowBase + warpM + mt * 16 + grp + h * 8;
                if (row >= M) continue;
                float v0 = acc[mt][nt][2 * h];
                float v1 = acc[mt][nt][2 * h + 1];
                if (mode == 3) {
                    v0 = fmaxf(v0 + b0, 0.f); v1 = fmaxf(v1 + b1, 0.f);
                    if (col < HID) {
                        ((uint32_t*)C)[(size_t)row * (HID / 2) + (col >> 1)] =
                            h2_as_u32(__floats2half2_rn(v0, v1));
                    } else {
                        *(float2*)(C2 + (size_t)row * OUTD + (col - HID)) = make_float2(v0, v1);
                    }
                } else if (mode == 4) {
                    ((uint32_t*)C)[(size_t)row * (N / 2) + (col >> 1)] =
                        h2_as_u32(__floats2half2_rn(v0 + b0, v1 + b1));
                } else if (mode == 2) {
                    float rd = 1.0f / (float)degv[row];
                    size_t base = (size_t)row * N + col;
                    v0 = fmaxf((v0 + addSrc[base])     * rd + b0, 0.f) + resid[base];
                    v1 = fmaxf((v1 + addSrc[base + 1]) * rd + b1, 0.f) + resid[base + 1];
                    *(float2*)(C + base) = make_float2(v0, v1);
                } else {
                    *(float2*)(C + (size_t)row * N + col) = make_float2(v0 + b0, v1 + b1);
                }
            }
        }
    }
}

// ---------------- edge kernel: 2 edges per block ----------------
__global__ __launch_bounds__(256)
void edge_kernel(const float* __restrict__ global_emb,
                 const int* __restrict__ edge_nodes,
                 const int* __restrict__ edge_size,
                 const int* __restrict__ node_degree,
                 int E)
{
    __shared__ int   s_nodes[2][4];
    __shared__ float s_scale[2][4];
    __shared__ int   s_size[2];

    const int half = threadIdx.x >> 7;
    const int lt   = threadIdx.x & 127;
    const int e    = blockIdx.x * 2 + half;
    const bool active = (e < E);

    if (active && lt < 4) {
        int sz = edge_size[e];
        if (lt == 0) s_size[half] = sz;
        int n = edge_nodes[e * 4 + lt];
        s_nodes[half][lt] = n;
        float a = (sz == 1) ? 1.0f : (sz <= 3 ? (1.0f / 3.0f) : 0.25f);
        s_scale[half][lt] = __powf((float)node_degree[n], a);
    }
    __syncthreads();
    if (!active) return;

    const int sz = s_size[half];
    const int k = 4 - sz;
    const float invf = (sz == 3) ? 0.5f : (sz == 4 ? (1.0f / 6.0f) : 1.0f);

    if (lt < RANK) {
        const int r = lt;
        float g = global_emb[r];
        float gf = (k == 0) ? 1.0f : (k == 1 ? g : g * g);
        float t[4];
        #pragma unroll
        for (int s = 0; s < 4; s++)
            t[s] = (s < sz) ? s_scale[half][s] * g_emb_new[s_nodes[half][s] * RANK + r] : 1.0f;
        float loo[4];
        loo[0] = t[1] * t[2] * t[3];
        loo[1] = t[0] * t[2] * t[3];
        loo[2] = t[0] * t[1] * t[3];
        loo[3] = t[0] * t[1] * t[2];
        float f = gf * invf;
        unsigned tb = (unsigned)e * (4u * RANK) + r;
        for (int s = 0; s < sz; s++)
            g_tee[tb + (unsigned)s * RANK] = __float2half_rn(tanhf(loo[s] * f));
    }

    {
        float sum0 = 0.f, sum1 = 0.f;
        for (int s = 0; s < sz; s++) {
            const __half2* row = (const __half2*)(g_emb_new2 + (unsigned)s_nodes[half][s] * OUTD);
            float2 v = __half22float2(row[lt]);
            sum0 += v.x;
            sum1 += v.y;
        }
        __half2* out = (__half2*)(g_esum2 + (unsigned)e * OUTD);
        out[lt] = __floats2half2_rn(fmaxf(sum0, 0.f), fmaxf(sum1, 0.f));
    }
}

// ---------------- node-major gather (unrolled x4, fp16 sources, fp32 accumulate) ----------------
__global__ __launch_bounds__(256)
void node_gather()
{
    int n = blockIdx.x;
    int tid = threadIdx.x;
    int s0 = g_offs[n], s1 = g_offs[n + 1];
    float acc0 = 0.f, acc1 = 0.f, acc2 = 0.f, acc3 = 0.f;
    float ar0 = 0.f, ar1 = 0.f, ar2 = 0.f, ar3 = 0.f;
    int j = s0;
    for (; j + 3 < s1; j += 4) {
        int cA = g_csr[j], cB = g_csr[j + 1], cC = g_csr[j + 2], cD = g_csr[j + 3];
        acc0 += __half2float(g_esum2[(unsigned)(cA >> 2) * OUTD + tid]);
        acc1 += __half2float(g_esum2[(unsigned)(cB >> 2) * OUTD + tid]);
        acc2 += __half2float(g_esum2[(unsigned)(cC >> 2) * OUTD + tid]);
        acc3 += __half2float(g_esum2[(unsigned)(cD >> 2) * OUTD + tid]);
        if (tid < RANK) {
            ar0 += __half2float(g_tee[(unsigned)cA * RANK + tid]);
            ar1 += __half2float(g_tee[(unsigned)cB * RANK + tid]);
            ar2 += __half2float(g_tee[(unsigned)cC * RANK + tid]);
            ar3 += __half2float(g_tee[(unsigned)cD * RANK + tid]);
        }
    }
    for (; j < s1; ++j) {
        int code = g_csr[j];
        acc0 += __half2float(g_esum2[(unsigned)(code >> 2) * OUTD + tid]);
        if (tid < RANK) ar0 += __half2float(g_tee[(unsigned)code * RANK + tid]);
    }
    g_nodeacc[(unsigned)n * OUTD + tid] = (acc0 + acc1) + (acc2 + acc3);
    if (tid < RANK)
        g_accRh[(unsigned)n * RANK + tid] = __float2half_rn((ar0 + ar1) + (ar2 + ar3));
}

// ---------------- launch ----------------
extern "C" void kernel_launch(void* const* d_in, const int* in_sizes, int n_in,
                              void* d_out, int out_size)
{
    const float* embedding  = (const float*)d_in[0];
    const float* global_emb = (const float*)d_in[1];
    const float* pW         = (const float*)d_in[2];
    const float* pb         = (const float*)d_in[3];
    const float* qW         = (const float*)d_in[4];
    const float* qb         = (const float*)d_in[5];
    const float* p2W1       = (const float*)d_in[6];
    const float* p2b1       = (const float*)d_in[7];
    const float* p2W2       = (const float*)d_in[8];
    const float* p2b2       = (const float*)d_in[9];
    const float* aW         = (const float*)d_in[10];
    const float* ab         = (const float*)d_in[11];
    const int*   edge_nodes = (const int*)d_in[12];
    const int*   edge_size  = (const int*)d_in[14];
    const int*   node_deg   = (const int*)d_in[15];
    const int*   inc_node   = (const int*)d_in[16];
    const int*   inc_edge   = (const int*)d_in[17];
    const int*   inc_slot   = (const int*)d_in[18];

    const int N    = in_sizes[0] / FEAT;
    const int E    = in_sizes[14];
    const int NINC = in_sizes[16];

    __half *p_embH, *p_hidden, *p_emb_new2, *p_accRh, *p_WtC, *p_Wt2, *p_WtP, *p_WtQ;
    float *p_emb_new, *p_residual, *p_nodeacc, *p_biasC, *p_biasP;
    int *p_offs, *p_cursor;
    cudaGetSymbolAddress((void**)&p_embH,     g_embH);
    cudaGetSymbolAddress((void**)&p_emb_new,  g_emb_new);
    cudaGetSymbolAddress((void**)&p_hidden,   g_hidden);
    cudaGetSymbolAddress((void**)&p_emb_new2, g_emb_new2);
    cudaGetSymbolAddress((void**)&p_residual, g_residual);
    cudaGetSymbolAddress((void**)&p_nodeacc,  g_nodeacc);
    cudaGetSymbolAddress((void**)&p_accRh,    g_accRh);
    cudaGetSymbolAddress((void**)&p_offs,     g_offs);
    cudaGetSymbolAddress((void**)&p_cursor,   g_cursor);
    cudaGetSymbolAddress((void**)&p_WtC,  g_WtC);
    cudaGetSymbolAddress((void**)&p_Wt2,  g_Wt2);
    cudaGetSymbolAddress((void**)&p_WtP,  g_WtP);
    cudaGetSymbolAddress((void**)&p_WtQ,  g_WtQ);
    cudaGetSymbolAddress((void**)&p_biasC, g_biasC);
    cudaGetSymbolAddress((void**)&p_biasP, g_biasP);

    const int SMEM128 = (2 * 128 * 20 + 2 * 128 * 20) * 4;  // 40960
    const int SMEM64  = (2 * 128 * 20 + 2 * 64  * 20) * 4;  // 30720
    cudaFuncSetAttribute(mma_gemm<128>, cudaFuncAttributeMaxDynamicSharedMemorySize, SMEM128);
    cudaFuncSetAttribute(mma_gemm<64>,  cudaFuncAttributeMaxDynamicSharedMemorySize, SMEM64);

    const int Mtiles = (N + 127) / 128;   // 235
    const int n4 = N * FEAT / 4;

    // 0: CSR offsets
    scan_offsets<<<1, 1024>>>(node_deg, p_offs, p_cursor, N);
    // 1: CSR fill
    csr_fill<<<(NINC + 255) / 256, 256>>>(inc_node, inc_edge, inc_slot, NINC);
    // 2: mega-prep
    prep_all<<<614 + (n4 + 255) / 256, 256>>>(embedding, p2W1, p2W2, aW, pW, qW,
                                              p2b1, ab, pb, n4);
    // 3 (ncu target): merged G2+G4: [hidden(h) | residual(f)] = relu(embH @ WtC^T + biasC)
    mma_gemm<128><<<dim3(NC / 128, Mtiles), 256, SMEM128>>>(
        p_embH, p_WtC, p_biasC, (float*)p_hidden, p_residual, N, NC, FEAT, 3,
        nullptr, nullptr, nullptr);
    // 4: G1 emb_new(f32) = embH @ pW^T + biasP                      [N x 64]
    mma_gemm<64><<<dim3(1, Mtiles), 256, SMEM64>>>(
        p_embH, p_WtP, p_biasP, p_emb_new, nullptr, N, RANK, FEAT, 0,
        nullptr, nullptr, nullptr);
    // 5: G3 emb_new2(h) = hidden @ p2W2 + p2b2   [N x 256], NT=64 (tail-wave fix)
    mma_gemm<64><<<dim3(OUTD / 64, Mtiles), 256, SMEM64>>>(
        p_hidden, p_Wt2, p2b2, (float*)p_emb_new2, nullptr, N, OUTD, HID, 4,
        nullptr, nullptr, nullptr);
    // 6: edge-level tanh(ee)(h) + relu(esum2)(h)
    edge_kernel<<<(E + 1) / 2, 256>>>(global_emb, edge_nodes, edge_size, node_deg, E);
    // 7: node-major gather
    node_gather<<<N, 256>>>();
    // 8: final fused GEMM, NT=64 (tail-wave fix)
    mma_gemm<64><<<dim3(OUTD / 64, Mtiles), 256, SMEM64>>>(
        p_accRh, p_WtQ, qb, (float*)d_out, nullptr, N, OUTD, RANK, 2,
        p_nodeacc, p_residual, node_deg);
}

// round 15
// speedup vs baseline: 1.0443x; 1.0443x over previous
#include <cuda_runtime.h>
#include <cuda_fp16.h>
#include <math.h>
#include <stdint.h>

// Problem constants
#define NN   30000
#define NE   60000
#define FEAT 256
#define HID  1024
#define OUTD 256
#define RANK 64
#define NC   1280   // HID + OUTD (merged G2+G4)

// ---------------- scratch (device globals) ----------------
__device__ __half g_embH    [NN * FEAT];
__device__ __half g_emb_newH[NN * RANK];     // fp16 emb_new
__device__ __half g_hidden  [NN * HID];
__device__ __half g_emb_new2[NN * OUTD];
__device__ float  g_residual[NN * OUTD];
__device__ __half g_tee     [NE * 4 * RANK];
__device__ __half g_esum2   [NE * OUTD];
__device__ float  g_nodeacc [NN * OUTD];
__device__ __half g_accRh   [NN * RANK];
__device__ int    g_offs    [NN + 1];
__device__ int    g_cursor  [NN];
__device__ int    g_csr     [NE * 4];
// K-major fp16 weights
__device__ __half g_WtC [NC * FEAT];
__device__ __half g_Wt2 [OUTD * HID];
__device__ __half g_WtP [RANK * FEAT];
__device__ __half g_WtQ [OUTD * RANK];
__device__ float  g_biasC [NC];
__device__ float  g_biasP [RANK];

// ---------------- helpers ----------------
__device__ __forceinline__ uint32_t smem_u32(const void* p) {
    uint32_t a;
    asm("{ .reg .u64 t; cvta.to.shared.u64 t, %1; cvt.u32.u64 %0, t; }" : "=r"(a) : "l"(p));
    return a;
}
__device__ __forceinline__ uint32_t h2_as_u32(__half2 h) {
    uint32_t u;
    memcpy(&u, &h, 4);
    return u;
}
__device__ __forceinline__ void cp16(uint32_t dst, const void* src, int szbytes) {
    asm volatile("cp.async.ca.shared.global [%0], [%1], 16, %2;"
                 :: "r"(dst), "l"(src), "r"(szbytes) : "memory");
}
#define CP_COMMIT() asm volatile("cp.async.commit_group;" ::: "memory")
#define CP_WAIT(n)  asm volatile("cp.async.wait_group %0;" :: "n"(n) : "memory")

__device__ __forceinline__ void mma16n8k16(float* d, const uint32_t* a, const uint32_t* b) {
    asm volatile(
        "mma.sync.aligned.m16n8k16.row.col.f32.f16.f16.f32 "
        "{%0,%1,%2,%3}, {%4,%5,%6,%7}, {%8,%9}, {%0,%1,%2,%3};"
        : "+f"(d[0]), "+f"(d[1]), "+f"(d[2]), "+f"(d[3])
        : "r"(a[0]), "r"(a[1]), "r"(a[2]), "r"(a[3]), "r"(b[0]), "r"(b[1]));
}
__device__ __forceinline__ void ldsm_x4(uint32_t* r, uint32_t addr) {
    asm volatile("ldmatrix.sync.aligned.m8n8.x4.shared.b16 {%0,%1,%2,%3}, [%4];"
        : "=r"(r[0]), "=r"(r[1]), "=r"(r[2]), "=r"(r[3]) : "r"(addr));
}

// ---------------- mega-prep ----------------
__global__ void prep_all(const float* __restrict__ emb,
                         const float* __restrict__ p2W1, const float* __restrict__ p2W2,
                         const float* __restrict__ aW,   const float* __restrict__ pW,
                         const float* __restrict__ qW,
                         const float* __restrict__ p2b1, const float* __restrict__ ab_,
                         const float* __restrict__ pb_,  int n4)
{
    __shared__ float t[32][33];
    const int bx = blockIdx.x;
    const int tid = threadIdx.x;
    if (bx < 608) {
        const float* W; __half* Wt; int K, N, t0;
        if      (bx < 256) { W = p2W1; Wt = g_WtC;              K = FEAT; N = HID;  t0 = 0;   }
        else if (bx < 512) { W = p2W2; Wt = g_Wt2;              K = HID;  N = OUTD; t0 = 256; }
        else if (bx < 576) { W = aW;   Wt = g_WtC + HID * FEAT; K = FEAT; N = OUTD; t0 = 512; }
        else if (bx < 592) { W = pW;   Wt = g_WtP;              K = FEAT; N = RANK; t0 = 576; }
        else               { W = qW;   Wt = g_WtQ;              K = RANK; N = OUTD; t0 = 592; }
        int tt = bx - t0;
        int tiles_n = N >> 5;
        int n0 = (tt % tiles_n) * 32, k0 = (tt / tiles_n) * 32;
        int tx = tid & 31, ty = tid >> 5;
        for (int i = ty; i < 32; i += 8)
            t[i][tx] = W[(k0 + i) * N + n0 + tx];
        __syncthreads();
        for (int i = ty; i < 32; i += 8)
            Wt[(n0 + i) * K + k0 + tx] = __float2half_rn(t[tx][i]);
    } else if (bx < 614) {
        int i = (bx - 608) * 256 + tid;
        if      (i < HID)        g_biasC[i] = p2b1[i] + p2W1[FEAT * HID + i];
        else if (i < HID + OUTD) g_biasC[i] = ab_[i - HID] + aW[FEAT * OUTD + (i - HID)];
        else if (i < HID + OUTD + RANK) g_biasP[i - HID - OUTD] = pb_[i - HID - OUTD] + pW[FEAT * RANK + (i - HID - OUTD)];
    } else {
        int i = (bx - 614) * 256 + tid;
        if (i < n4) {
            float4 v = ((const float4*)emb)[i];
            uint2 o;
            o.x = h2_as_u32(__floats2half2_rn(v.x, v.y));
            o.y = h2_as_u32(__floats2half2_rn(v.z, v.w));
            ((uint2*)g_embH)[i] = o;
        }
    }
}

// ---------------- CSR offsets ----------------
__global__ __launch_bounds__(1024)
void scan_offsets(const int* __restrict__ deg, int* __restrict__ offs,
                  int* __restrict__ cursor, int N)
{
    constexpr int CE = 32;
    const int tid = threadIdx.x;
    const int start = tid * CE;

    int local = 0;
    if (start < N) {
        #pragma unroll
        for (int j = 0; j < CE; j += 4) {
            int i = start + j;
            if (i + 3 < N) {
                int4 v = *(const int4*)(deg + i);
                local += v.x + v.y + v.z + v.w;
            } else {
                #pragma unroll
                for (int k = 0; k < 4; k++) if (i + k < N) local += deg[i + k];
            }
        }
    }
    __shared__ int warpsum[32];
    int lane = tid & 31, w = tid >> 5;
    int x = local;
    #pragma unroll
    for (int o = 1; o < 32; o <<= 1) { int y = __shfl_up_sync(~0u, x, o); if (lane >= o) x += y; }
    if (lane == 31) warpsum[w] = x;
    __syncthreads();
    if (w == 0) {
        int s = warpsum[lane];
        #pragma unroll
        for (int o = 1; o < 32; o <<= 1) { int y = __shfl_up_sync(~0u, s, o); if (lane >= o) s += y; }
        warpsum[lane] = s;
    }
    __syncthreads();
    int base = x - local + (w > 0 ? warpsum[w - 1] : 0);

    if (start < N) {
        int run = base;
        #pragma unroll
        for (int j = 0; j < CE; j++) {
            int i = start + j;
            if (i < N) { offs[i] = run; cursor[i] = 0; run += deg[i]; }
        }
        if (tid == (N - 1) / CE) offs[N] = run;
    }
}

__global__ void csr_fill(const int* __restrict__ inc_node, const int* __restrict__ inc_edge,
                         const int* __restrict__ inc_slot, int NINC)
{
    int i = blockIdx.x * blockDim.x + threadIdx.x;
    if (i < NINC) {
        int n = inc_node[i];
        int p = atomicAdd(&g_cursor[n], 1);
        g_csr[g_offs[n] + p] = (inc_edge[i] << 2) | inc_slot[i];
    }
}

// ---------------- fp16 tensor-core GEMM (m16n8k16 + ldmatrix) ----------------
// mode 0: C(f32) = acc + bias
// mode 2: C(f32) = relu((acc + addSrc)/deg + bias) + resid
// mode 3: col<HID -> relu -> half2 (stride HID); else relu -> f32 C2 (stride OUTD)
// mode 4: C = half2(acc + bias), stride N (fp16 output, no relu)
template<int NT>
__global__ __launch_bounds__(256, 2)
void mma_gemm(const __half* __restrict__ A, const __half* __restrict__ Bt,
              const float* __restrict__ bias,
              float* __restrict__ C, float* __restrict__ C2,
              int M, int N, int K, int mode,
              const float* __restrict__ addSrc, const float* __restrict__ resid,
              const int* __restrict__ degv)
{
    constexpr int STW = 20;
    constexpr int NTILES = NT / 16;
    extern __shared__ uint32_t dyn32[];
    uint32_t* Asm = dyn32;
    uint32_t* Bsm = dyn32 + 2 * 128 * STW;

    const int tid  = threadIdx.x;
    const int wid  = tid >> 5;
    const int lane = tid & 31;
    const int grp  = lane >> 2;
    const int tig  = lane & 3;
    const int warpM = (wid & 3) * 32;
    const int warpN = (wid >> 2) * (NT / 2);
    const int rowBase = blockIdx.y * 128;
    const int colBase = blockIdx.x * NT;

    float acc[2][NTILES][4];
    #pragma unroll
    for (int mt = 0; mt < 2; mt++)
        #pragma unroll
        for (int nt = 0; nt < NTILES; nt++)
            #pragma unroll
            for (int i = 0; i < 4; i++) acc[mt][nt][i] = 0.f;

    const uint32_t asm_base = smem_u32(Asm);
    const uint32_t bsm_base = smem_u32(Bsm);

    const int lrow8 = lane & 7;
    const int a_row_off = lrow8 + (((lane >> 3) & 1) << 3);
    const int a_col_off = ((lane >> 4) << 2);
    const int b_row_off = lrow8 + ((lane >> 4) << 3);
    const int b_col_off = (((lane >> 3) & 1) << 2);

    auto loadChunk = [&](int c, int buf) {
        #pragma unroll
        for (int i = 0; i < 2; i++) {
            int idx = tid + (i << 8);
            int r = idx >> 2, seg = idx & 3;
            int gr = rowBase + r;
            const __half* src = A + (size_t)gr * K + (c << 5) + (seg << 3);
            uint32_t dst = asm_base + (buf * 128 * STW + r * STW + (seg << 2)) * 4;
            cp16(dst, src, gr < M ? 16 : 0);
        }
        #pragma unroll
        for (int i = 0; i < NT / 64; i++) {
            int idx = tid + (i << 8);
            int r = idx >> 2, seg = idx & 3;
            const __half* src = Bt + (size_t)(colBase + r) * K + (c << 5) + (seg << 3);
            uint32_t dst = bsm_base + (buf * NT * STW + r * STW + (seg << 2)) * 4;
            cp16(dst, src, 16);
        }
        CP_COMMIT();
    };

    const int nch = K >> 5;
    loadChunk(0, 0);

    for (int c = 0; c < nch; ++c) {
        const int buf = c & 1;
        if (c + 1 < nch) { loadChunk(c + 1, buf ^ 1); CP_WAIT(1); }
        else             { CP_WAIT(0); }
        __syncthreads();

        const uint32_t abase = asm_base + (buf * 128 * STW) * 4;
        const uint32_t bbase = bsm_base + (buf * NT * STW) * 4;
        #pragma unroll
        for (int ks = 0; ks < 2; ++ks) {
            const int kw = ks << 3;
            uint32_t afr[2][4];
            #pragma unroll
            for (int mt = 0; mt < 2; mt++) {
                uint32_t ad = abase +
                    ((warpM + mt * 16 + a_row_off) * STW + kw + a_col_off) * 4;
                ldsm_x4(afr[mt], ad);
            }
            uint32_t bfr[NTILES][2];
            #pragma unroll
            for (int p = 0; p < NTILES / 2; p++) {
                uint32_t bd = bbase +
                    ((warpN + p * 16 + b_row_off) * STW + kw + b_col_off) * 4;
                uint32_t r4[4];
                ldsm_x4(r4, bd);
                bfr[2 * p][0] = r4[0]; bfr[2 * p][1] = r4[1];
                bfr[2 * p + 1][0] = r4[2]; bfr[2 * p + 1][1] = r4[3];
            }
            #pragma unroll
            for (int mt = 0; mt < 2; mt++)
                #pragma unroll
                for (int nt = 0; nt < NTILES; nt++)
                    mma16n8k16(acc[mt][nt], afr[mt], bfr[nt]);
        }
        __syncthreads();
    }

    #pragma unroll
    for (int mt = 0; mt < 2; mt++) {
        #pragma unroll
        for (int nt = 0; nt < NTILES; nt++) {
            int col = colBase + warpN + nt * 8 + (tig << 1);
            float b0 = bias[col], b1 = bias[col + 1];
            #pragma unroll
            for (int h = 0; h < 2; h++) {
                int row = rowBase + warpM + mt * 16 + grp + h * 8;
                if (row >= M) continue;
                float v0 = acc[mt][nt][2 * h];
                float v1 = acc[mt][nt][2 * h + 1];
                if (mode == 3) {
                    v0 = fmaxf(v0 + b0, 0.f); v1 = fmaxf(v1 + b1, 0.f);
                    if (col < HID) {
                        ((uint32_t*)C)[(size_t)row * (HID / 2) + (col >> 1)] =
                            h2_as_u32(__floats2half2_rn(v0, v1));
                    } else {
                        *(float2*)(C2 + (size_t)row * OUTD + (col - HID)) = make_float2(v0, v1);
                    }
                } else if (mode == 4) {
                    ((uint32_t*)C)[(size_t)row * (N / 2) + (col >> 1)] =
                        h2_as_u32(__floats2half2_rn(v0 + b0, v1 + b1));
                } else if (mode == 2) {
                    float rd = 1.0f / (float)degv[row];
                    size_t base = (size_t)row * N + col;
                    v0 = fmaxf((v0 + addSrc[base])     * rd + b0, 0.f) + resid[base];
                    v1 = fmaxf((v1 + addSrc[base + 1]) * rd + b1, 0.f) + resid[base + 1];
                    *(float2*)(C + base) = make_float2(v0, v1);
                } else {
                    *(float2*)(C + (size_t)row * N + col) = make_float2(v0 + b0, v1 + b1);
                }
            }
        }
    }
}

// ---------------- edge kernel: 2 edges per block; fp16 emb_new ----------------
__global__ __launch_bounds__(256)
void edge_kernel(const float* __restrict__ global_emb,
                 const int* __restrict__ edge_nodes,
                 const int* __restrict__ edge_size,
                 const int* __restrict__ node_degree,
                 int E)
{
    __shared__ int   s_nodes[2][4];
    __shared__ float s_scale[2][4];
    __shared__ int   s_size[2];

    const int half = threadIdx.x >> 7;
    const int lt   = threadIdx.x & 127;
    const int e    = blockIdx.x * 2 + half;
    const bool active = (e < E);

    if (active && lt < 4) {
        int sz = edge_size[e];
        if (lt == 0) s_size[half] = sz;
        int n = edge_nodes[e * 4 + lt];
        s_nodes[half][lt] = n;
        float a = (sz == 1) ? 1.0f : (sz <= 3 ? (1.0f / 3.0f) : 0.25f);
        s_scale[half][lt] = __powf((float)node_degree[n], a);
    }
    __syncthreads();
    if (!active) return;

    const int sz = s_size[half];
    const int k = 4 - sz;
    const float invf = (sz == 3) ? 0.5f : (sz == 4 ? (1.0f / 6.0f) : 1.0f);

    if (lt < RANK) {
        const int r = lt;
        float g = global_emb[r];
        float gf = (k == 0) ? 1.0f : (k == 1 ? g : g * g);
        float t[4];
        #pragma unroll
        for (int s = 0; s < 4; s++)
            t[s] = (s < sz) ? s_scale[half][s] *
                   __half2float(g_emb_newH[(unsigned)s_nodes[half][s] * RANK + r]) : 1.0f;
        float loo[4];
        loo[0] = t[1] * t[2] * t[3];
        loo[1] = t[0] * t[2] * t[3];
        loo[2] = t[0] * t[1] * t[3];
        loo[3] = t[0] * t[1] * t[2];
        float f = gf * invf;
        unsigned tb = (unsigned)e * (4u * RANK) + r;
        for (int s = 0; s < sz; s++)
            g_tee[tb + (unsigned)s * RANK] = __float2half_rn(tanhf(loo[s] * f));
    }

    {
        float sum0 = 0.f, sum1 = 0.f;
        for (int s = 0; s < sz; s++) {
            const __half2* row = (const __half2*)(g_emb_new2 + (unsigned)s_nodes[half][s] * OUTD);
            float2 v = __half22float2(row[lt]);
            sum0 += v.x;
            sum1 += v.y;
        }
        __half2* out = (__half2*)(g_esum2 + (unsigned)e * OUTD);
        out[lt] = __floats2half2_rn(fmaxf(sum0, 0.f), fmaxf(sum1, 0.f));
    }
}

// ---------------- node-major gather (unrolled x4, fp16 sources, fp32 accumulate) ----------------
__global__ __launch_bounds__(256)
void node_gather()
{
    int n = blockIdx.x;
    int tid = threadIdx.x;
    int s0 = g_offs[n], s1 = g_offs[n + 1];
    float acc0 = 0.f, acc1 = 0.f, acc2 = 0.f, acc3 = 0.f;
    float ar0 = 0.f, ar1 = 0.f, ar2 = 0.f, ar3 = 0.f;
    int j = s0;
    for (; j + 3 < s1; j += 4) {
        int cA = g_csr[j], cB = g_csr[j + 1], cC = g_csr[j + 2], cD = g_csr[j + 3];
        acc0 += __half2float(g_esum2[(unsigned)(cA >> 2) * OUTD + tid]);
        acc1 += __half2float(g_esum2[(unsigned)(cB >> 2) * OUTD + tid]);
        acc2 += __half2float(g_esum2[(unsigned)(cC >> 2) * OUTD + tid]);
        acc3 += __half2float(g_esum2[(unsigned)(cD >> 2) * OUTD + tid]);
        if (tid < RANK) {
            ar0 += __half2float(g_tee[(unsigned)cA * RANK + tid]);
            ar1 += __half2float(g_tee[(unsigned)cB * RANK + tid]);
            ar2 += __half2float(g_tee[(unsigned)cC * RANK + tid]);
            ar3 += __half2float(g_tee[(unsigned)cD * RANK + tid]);
        }
    }
    for (; j < s1; ++j) {
        int code = g_csr[j];
        acc0 += __half2float(g_esum2[(unsigned)(code >> 2) * OUTD + tid]);
        if (tid < RANK) ar0 += __half2float(g_tee[(unsigned)code * RANK + tid]);
    }
    g_nodeacc[(unsigned)n * OUTD + tid] = (acc0 + acc1) + (acc2 + acc3);
    if (tid < RANK)
        g_accRh[(unsigned)n * RANK + tid] = __float2half_rn((ar0 + ar1) + (ar2 + ar3));
}

// ---------------- launch ----------------
extern "C" void kernel_launch(void* const* d_in, const int* in_sizes, int n_in,
                              void* d_out, int out_size)
{
    const float* embedding  = (const float*)d_in[0];
    const float* global_emb = (const float*)d_in[1];
    const float* pW         = (const float*)d_in[2];
    const float* pb         = (const float*)d_in[3];
    const float* qW         = (const float*)d_in[4];
    const float* qb         = (const float*)d_in[5];
    const float* p2W1       = (const float*)d_in[6];
    const float* p2b1       = (const float*)d_in[7];
    const float* p2W2       = (const float*)d_in[8];
    const float* p2b2       = (const float*)d_in[9];
    const float* aW         = (const float*)d_in[10];
    const float* ab         = (const float*)d_in[11];
    const int*   edge_nodes = (const int*)d_in[12];
    const int*   edge_size  = (const int*)d_in[14];
    const int*   node_deg   = (const int*)d_in[15];
    const int*   inc_node   = (const int*)d_in[16];
    const int*   inc_edge   = (const int*)d_in[17];
    const int*   inc_slot   = (const int*)d_in[18];

    const int N    = in_sizes[0] / FEAT;
    const int E    = in_sizes[14];
    const int NINC = in_sizes[16];

    __half *p_embH, *p_emb_newH, *p_hidden, *p_emb_new2, *p_accRh, *p_WtC, *p_Wt2, *p_WtP, *p_WtQ;
    float *p_residual, *p_nodeacc, *p_biasC, *p_biasP;
    int *p_offs, *p_cursor;
    cudaGetSymbolAddress((void**)&p_embH,     g_embH);
    cudaGetSymbolAddress((void**)&p_emb_newH, g_emb_newH);
    cudaGetSymbolAddress((void**)&p_hidden,   g_hidden);
    cudaGetSymbolAddress((void**)&p_emb_new2, g_emb_new2);
    cudaGetSymbolAddress((void**)&p_residual, g_residual);
    cudaGetSymbolAddress((void**)&p_nodeacc,  g_nodeacc);
    cudaGetSymbolAddress((void**)&p_accRh,    g_accRh);
    cudaGetSymbolAddress((void**)&p_offs,     g_offs);
    cudaGetSymbolAddress((void**)&p_cursor,   g_cursor);
    cudaGetSymbolAddress((void**)&p_WtC,  g_WtC);
    cudaGetSymbolAddress((void**)&p_Wt2,  g_Wt2);
    cudaGetSymbolAddress((void**)&p_WtP,  g_WtP);
    cudaGetSymbolAddress((void**)&p_WtQ,  g_WtQ);
    cudaGetSymbolAddress((void**)&p_biasC, g_biasC);
    cudaGetSymbolAddress((void**)&p_biasP, g_biasP);

    const int SMEM128 = (2 * 128 * 20 + 2 * 128 * 20) * 4;  // 40960
    const int SMEM64  = (2 * 128 * 20 + 2 * 64  * 20) * 4;  // 30720
    cudaFuncSetAttribute(mma_gemm<128>, cudaFuncAttributeMaxDynamicSharedMemorySize, SMEM128);
    cudaFuncSetAttribute(mma_gemm<64>,  cudaFuncAttributeMaxDynamicSharedMemorySize, SMEM64);

    const int Mtiles = (N + 127) / 128;   // 235
    const int n4 = N * FEAT / 4;

    // 0: CSR offsets
    scan_offsets<<<1, 1024>>>(node_deg, p_offs, p_cursor, N);
    // 1: CSR fill
    csr_fill<<<(NINC + 255) / 256, 256>>>(inc_node, inc_edge, inc_slot, NINC);
    // 2: mega-prep
    prep_all<<<614 + (n4 + 255) / 256, 256>>>(embedding, p2W1, p2W2, aW, pW, qW,
                                              p2b1, ab, pb, n4);
    // 3 (ncu target): merged G2+G4: [hidden(h) | residual(f)] = relu(embH @ WtC^T + biasC)
    mma_gemm<128><<<dim3(NC / 128, Mtiles), 256, SMEM128>>>(
        p_embH, p_WtC, p_biasC, (float*)p_hidden, p_residual, N, NC, FEAT, 3,
        nullptr, nullptr, nullptr);
    // 4: G1 emb_new(h) = embH @ pW^T + biasP                      [N x 64]
    mma_gemm<64><<<dim3(1, Mtiles), 256, SMEM64>>>(
        p_embH, p_WtP, p_biasP, (float*)p_emb_newH, nullptr, N, RANK, FEAT, 4,
        nullptr, nullptr, nullptr);
    // 5: G3 emb_new2(h) = hidden @ p2W2 + p2b2   [N x 256], NT=128
    mma_gemm<128><<<dim3(OUTD / 128, Mtiles), 256, SMEM128>>>(
        p_hidden, p_Wt2, p2b2, (float*)p_emb_new2, nullptr, N, OUTD, HID, 4,
        nullptr, nullptr, nullptr);
    // 6: edge-level tanh(ee)(h) + relu(esum2)(h)
    edge_kernel<<<(E + 1) / 2, 256>>>(global_emb, edge_nodes, edge_size, node_deg, E);
    // 7: node-major gather
    node_gather<<<N, 256>>>();
    // 8: final fused GEMM, NT=128
    mma_gemm<128><<<dim3(OUTD / 128, Mtiles), 256, SMEM128>>>(
        p_accRh, p_WtQ, qb, (float*)d_out, nullptr, N, OUTD, RANK, 2,
        p_nodeacc, p_residual, node_deg);
}

// round 16
// speedup vs baseline: 1.0548x; 1.0101x over previous
#include <cuda_runtime.h>
#include <cuda_fp16.h>
#include <math.h>
#include <stdint.h>

// Problem constants
#define NN   30000
#define NE   60000
#define FEAT 256
#define HID  1024
#define OUTD 256
#define RANK 64
#define NC   1280   // HID + OUTD (merged G2+G4)

// ---------------- scratch (device globals) ----------------
__device__ __half g_embH    [NN * FEAT];
__device__ float  g_emb_new [NN * RANK];     // fp32 (R13 proven)
__device__ __half g_hidden  [NN * HID];
__device__ __half g_emb_new2[NN * OUTD];
__device__ float  g_residual[NN * OUTD];
__device__ __half g_tee     [NE * 4 * RANK];
__device__ __half g_esum2   [NE * OUTD];
__device__ float  g_nodeacc [NN * OUTD];
__device__ __half g_accRh   [NN * RANK];
__device__ int    g_offs    [NN + 1];
__device__ int    g_cursor  [NN];
__device__ int    g_csr     [NE * 4];
// K-major fp16 weights
__device__ __half g_WtC [NC * FEAT];
__device__ __half g_Wt2 [OUTD * HID];
__device__ __half g_WtP [RANK * FEAT];
__device__ __half g_WtQ [OUTD * RANK];
__device__ float  g_biasC [NC];
__device__ float  g_biasP [RANK];

// ---------------- helpers ----------------
__device__ __forceinline__ uint32_t smem_u32(const void* p) {
    uint32_t a;
    asm("{ .reg .u64 t; cvta.to.shared.u64 t, %1; cvt.u32.u64 %0, t; }" : "=r"(a) : "l"(p));
    return a;
}
__device__ __forceinline__ uint32_t h2_as_u32(__half2 h) {
    uint32_t u;
    memcpy(&u, &h, 4);
    return u;
}
__device__ __forceinline__ void cp16(uint32_t dst, const void* src, int szbytes) {
    asm volatile("cp.async.ca.shared.global [%0], [%1], 16, %2;"
                 :: "r"(dst), "l"(src), "r"(szbytes) : "memory");
}
#define CP_COMMIT() asm volatile("cp.async.commit_group;" ::: "memory")
#define CP_WAIT(n)  asm volatile("cp.async.wait_group %0;" :: "n"(n) : "memory")

__device__ __forceinline__ void mma16n8k16(float* d, const uint32_t* a, const uint32_t* b) {
    asm volatile(
        "mma.sync.aligned.m16n8k16.row.col.f32.f16.f16.f32 "
        "{%0,%1,%2,%3}, {%4,%5,%6,%7}, {%8,%9}, {%0,%1,%2,%3};"
        : "+f"(d[0]), "+f"(d[1]), "+f"(d[2]), "+f"(d[3])
        : "r"(a[0]), "r"(a[1]), "r"(a[2]), "r"(a[3]), "r"(b[0]), "r"(b[1]));
}
__device__ __forceinline__ void ldsm_x4(uint32_t* r, uint32_t addr) {
    asm volatile("ldmatrix.sync.aligned.m8n8.x4.shared.b16 {%0,%1,%2,%3}, [%4];"
        : "=r"(r[0]), "=r"(r[1]), "=r"(r[2]), "=r"(r[3]) : "r"(addr));
}

// ---------------- mega-prep ----------------
__global__ void prep_all(const float* __restrict__ emb,
                         const float* __restrict__ p2W1, const float* __restrict__ p2W2,
                         const float* __restrict__ aW,   const float* __restrict__ pW,
                         const float* __restrict__ qW,
                         const float* __restrict__ p2b1, const float* __restrict__ ab_,
                         const float* __restrict__ pb_,  int n4)
{
    __shared__ float t[32][33];
    const int bx = blockIdx.x;
    const int tid = threadIdx.x;
    if (bx < 608) {
        const float* W; __half* Wt; int K, N, t0;
        if      (bx < 256) { W = p2W1; Wt = g_WtC;              K = FEAT; N = HID;  t0 = 0;   }
        else if (bx < 512) { W = p2W2; Wt = g_Wt2;              K = HID;  N = OUTD; t0 = 256; }
        else if (bx < 576) { W = aW;   Wt = g_WtC + HID * FEAT; K = FEAT; N = OUTD; t0 = 512; }
        else if (bx < 592) { W = pW;   Wt = g_WtP;              K = FEAT; N = RANK; t0 = 576; }
        else               { W = qW;   Wt = g_WtQ;              K = RANK; N = OUTD; t0 = 592; }
        int tt = bx - t0;
        int tiles_n = N >> 5;
        int n0 = (tt % tiles_n) * 32, k0 = (tt / tiles_n) * 32;
        int tx = tid & 31, ty = tid >> 5;
        for (int i = ty; i < 32; i += 8)
            t[i][tx] = W[(k0 + i) * N + n0 + tx];
        __syncthreads();
        for (int i = ty; i < 32; i += 8)
            Wt[(n0 + i) * K + k0 + tx] = __float2half_rn(t[tx][i]);
    } else if (bx < 614) {
        int i = (bx - 608) * 256 + tid;
        if      (i < HID)        g_biasC[i] = p2b1[i] + p2W1[FEAT * HID + i];
        else if (i < HID + OUTD) g_biasC[i] = ab_[i - HID] + aW[FEAT * OUTD + (i - HID)];
        else if (i < HID + OUTD + RANK) g_biasP[i - HID - OUTD] = pb_[i - HID - OUTD] + pW[FEAT * RANK + (i - HID - OUTD)];
    } else {
        int i = (bx - 614) * 256 + tid;
        if (i < n4) {
            float4 v = ((const float4*)emb)[i];
            uint2 o;
            o.x = h2_as_u32(__floats2half2_rn(v.x, v.y));
            o.y = h2_as_u32(__floats2half2_rn(v.z, v.w));
            ((uint2*)g_embH)[i] = o;
        }
    }
}

// ---------------- CSR offsets ----------------
__global__ __launch_bounds__(1024)
void scan_offsets(const int* __restrict__ deg, int* __restrict__ offs,
                  int* __restrict__ cursor, int N)
{
    constexpr int CE = 32;
    const int tid = threadIdx.x;
    const int start = tid * CE;

    int local = 0;
    if (start < N) {
        #pragma unroll
        for (int j = 0; j < CE; j += 4) {
            int i = start + j;
            if (i + 3 < N) {
                int4 v = *(const int4*)(deg + i);
                local += v.x + v.y + v.z + v.w;
            } else {
                #pragma unroll
                for (int k = 0; k < 4; k++) if (i + k < N) local += deg[i + k];
            }
        }
    }
    __shared__ int warpsum[32];
    int lane = tid & 31, w = tid >> 5;
    int x = local;
    #pragma unroll
    for (int o = 1; o < 32; o <<= 1) { int y = __shfl_up_sync(~0u, x, o); if (lane >= o) x += y; }
    if (lane == 31) warpsum[w] = x;
    __syncthreads();
    if (w == 0) {
        int s = warpsum[lane];
        #pragma unroll
        for (int o = 1; o < 32; o <<= 1) { int y = __shfl_up_sync(~0u, s, o); if (lane >= o) s += y; }
        warpsum[lane] = s;
    }
    __syncthreads();
    int base = x - local + (w > 0 ? warpsum[w - 1] : 0);

    if (start < N) {
        int run = base;
        #pragma unroll
        for (int j = 0; j < CE; j++) {
            int i = start + j;
            if (i < N) { offs[i] = run; cursor[i] = 0; run += deg[i]; }
        }
        if (tid == (N - 1) / CE) offs[N] = run;
    }
}

__global__ void csr_fill(const int* __restrict__ inc_node, const int* __restrict__ inc_edge,
                         const int* __restrict__ inc_slot, int NINC)
{
    int i = blockIdx.x * blockDim.x + threadIdx.x;
    if (i < NINC) {
        int n = inc_node[i];
        int p = atomicAdd(&g_cursor[n], 1);
        g_csr[g_offs[n] + p] = (inc_edge[i] << 2) | inc_slot[i];
    }
}

// ---------------- fp16 tensor-core GEMM (m16n8k16 + ldmatrix + 3-stage pipeline) ----------------
// mode 0: C(f32) = acc + bias
// mode 2: C(f32) = relu((acc + addSrc)/deg + bias) + resid
// mode 3: col<HID -> relu -> half2 (stride HID); else relu -> f32 C2 (stride OUTD)
// mode 4: C = half2(acc + bias), stride N (fp16 output, no relu)
template<int NT>
__global__ __launch_bounds__(256, 2)
void mma_gemm(const __half* __restrict__ A, const __half* __restrict__ Bt,
              const float* __restrict__ bias,
              float* __restrict__ C, float* __restrict__ C2,
              int M, int N, int K, int mode,
              const float* __restrict__ addSrc, const float* __restrict__ resid,
              const int* __restrict__ degv)
{
    constexpr int STW = 20;
    constexpr int NTILES = NT / 16;
    extern __shared__ uint32_t dyn32[];
    uint32_t* Asm = dyn32;                   // 3 bufs x 128 x STW words
    uint32_t* Bsm = dyn32 + 3 * 128 * STW;   // 3 bufs x NT x STW words

    const int tid  = threadIdx.x;
    const int wid  = tid >> 5;
    const int lane = tid & 31;
    const int grp  = lane >> 2;
    const int tig  = lane & 3;
    const int warpM = (wid & 3) * 32;
    const int warpN = (wid >> 2) * (NT / 2);
    const int rowBase = blockIdx.y * 128;
    const int colBase = blockIdx.x * NT;

    float acc[2][NTILES][4];
    #pragma unroll
    for (int mt = 0; mt < 2; mt++)
        #pragma unroll
        for (int nt = 0; nt < NTILES; nt++)
            #pragma unroll
            for (int i = 0; i < 4; i++) acc[mt][nt][i] = 0.f;

    const uint32_t asm_base = smem_u32(Asm);
    const uint32_t bsm_base = smem_u32(Bsm);

    const int lrow8 = lane & 7;
    const int a_row_off = lrow8 + (((lane >> 3) & 1) << 3);
    const int a_col_off = ((lane >> 4) << 2);
    const int b_row_off = lrow8 + ((lane >> 4) << 3);
    const int b_col_off = (((lane >> 3) & 1) << 2);

    auto loadChunk = [&](int c, int buf) {
        #pragma unroll
        for (int i = 0; i < 2; i++) {
            int idx = tid + (i << 8);
            int r = idx >> 2, seg = idx & 3;
            int gr = rowBase + r;
            const __half* src = A + (size_t)gr * K + (c << 5) + (seg << 3);
            uint32_t dst = asm_base + (buf * 128 * STW + r * STW + (seg << 2)) * 4;
            cp16(dst, src, gr < M ? 16 : 0);
        }
        #pragma unroll
        for (int i = 0; i < NT / 64; i++) {
            int idx = tid + (i << 8);
            int r = idx >> 2, seg = idx & 3;
            const __half* src = Bt + (size_t)(colBase + r) * K + (c << 5) + (seg << 3);
            uint32_t dst = bsm_base + (buf * NT * STW + r * STW + (seg << 2)) * 4;
            cp16(dst, src, 16);
        }
        CP_COMMIT();
    };

    const int nch = K >> 5;                // >= 2 for all our shapes
    loadChunk(0, 0);
    loadChunk(1, 1);

    int buf = 0;
    for (int c = 0; c < nch; ++c) {
        if (c + 1 < nch) { CP_WAIT(1); }   // chunk c landed (c+1 may still fly)
        else             { CP_WAIT(0); }   // last chunk must be complete
        __syncthreads();                   // publish chunk c; all warps done with chunk c-1
        if (c + 2 < nch) {
            int nb = buf + 2; if (nb >= 3) nb -= 3;
            loadChunk(c + 2, nb);          // writes buffer of chunk c-1 (safe post-barrier)
        }

        const uint32_t abase = asm_base + (buf * 128 * STW) * 4;
        const uint32_t bbase = bsm_base + (buf * NT * STW) * 4;
        #pragma unroll
        for (int ks = 0; ks < 2; ++ks) {
            const int kw = ks << 3;
            uint32_t afr[2][4];
            #pragma unroll
            for (int mt = 0; mt < 2; mt++) {
                uint32_t ad = abase +
                    ((warpM + mt * 16 + a_row_off) * STW + kw + a_col_off) * 4;
                ldsm_x4(afr[mt], ad);
            }
            uint32_t bfr[NTILES][2];
            #pragma unroll
            for (int p = 0; p < NTILES / 2; p++) {
                uint32_t bd = bbase +
                    ((warpN + p * 16 + b_row_off) * STW + kw + b_col_off) * 4;
                uint32_t r4[4];
                ldsm_x4(r4, bd);
                bfr[2 * p][0] = r4[0]; bfr[2 * p][1] = r4[1];
                bfr[2 * p + 1][0] = r4[2]; bfr[2 * p + 1][1] = r4[3];
            }
            #pragma unroll
            for (int mt = 0; mt < 2; mt++)
                #pragma unroll
                for (int nt = 0; nt < NTILES; nt++)
                    mma16n8k16(acc[mt][nt], afr[mt], bfr[nt]);
        }
        buf++; if (buf >= 3) buf = 0;
    }

    #pragma unroll
    for (int mt = 0; mt < 2; mt++) {
        #pragma unroll
        for (int nt = 0; nt < NTILES; nt++) {
            int col = colBase + warpN + nt * 8 + (tig << 1);
            float b0 = bias[col], b1 = bias[col + 1];
            #pragma unroll
            for (int h = 0; h < 2; h++) {
                int row = rowBase + warpM + mt * 16 + grp + h * 8;
                if (row >= M) continue;
                float v0 = acc[mt][nt][2 * h];
                float v1 = acc[mt][nt][2 * h + 1];
                if (mode == 3) {
                    v0 = fmaxf(v0 + b0, 0.f); v1 = fmaxf(v1 + b1, 0.f);
                    if (col < HID) {
                        ((uint32_t*)C)[(size_t)row * (HID / 2) + (col >> 1)] =
                            h2_as_u32(__floats2half2_rn(v0, v1));
                    } else {
                        *(float2*)(C2 + (size_t)row * OUTD + (col - HID)) = make_float2(v0, v1);
                    }
                } else if (mode == 4) {
                    ((uint32_t*)C)[(size_t)row * (N / 2) + (col >> 1)] =
                        h2_as_u32(__floats2half2_rn(v0 + b0, v1 + b1));
                } else if (mode == 2) {
                    float rd = 1.0f / (float)degv[row];
                    size_t base = (size_t)row * N + col;
                    v0 = fmaxf((v0 + addSrc[base])     * rd + b0, 0.f) + resid[base];
                    v1 = fmaxf((v1 + addSrc[base + 1]) * rd + b1, 0.f) + resid[base + 1];
                    *(float2*)(C + base) = make_float2(v0, v1);
                } else {
                    *(float2*)(C + (size_t)row * N + col) = make_float2(v0 + b0, v1 + b1);
                }
            }
        }
    }
}

// ---------------- edge kernel: 2 edges per block (R13 state: fp32 emb_new) ----------------
__global__ __launch_bounds__(256)
void edge_kernel(const float* __restrict__ global_emb,
                 const int* __restrict__ edge_nodes,
                 const int* __restrict__ edge_size,
                 const int* __restrict__ node_degree,
                 int E)
{
    __shared__ int   s_nodes[2][4];
    __shared__ float s_scale[2][4];
    __shared__ int   s_size[2];

    const int half = threadIdx.x >> 7;
    const int lt   = threadIdx.x & 127;
    const int e    = blockIdx.x * 2 + half;
    const bool active = (e < E);

    if (active && lt < 4) {
        int sz = edge_size[e];
        if (lt == 0) s_size[half] = sz;
        int n = edge_nodes[e * 4 + lt];
        s_nodes[half][lt] = n;
        float a = (sz == 1) ? 1.0f : (sz <= 3 ? (1.0f / 3.0f) : 0.25f);
        s_scale[half][lt] = __powf((float)node_degree[n], a);
    }
    __syncthreads();
    if (!active) return;

    const int sz = s_size[half];
    const int k = 4 - sz;
    const float invf = (sz == 3) ? 0.5f : (sz == 4 ? (1.0f / 6.0f) : 1.0f);

    if (lt < RANK) {
        const int r = lt;
        float g = global_emb[r];
        float gf = (k == 0) ? 1.0f : (k == 1 ? g : g * g);
        float t[4];
        #pragma unroll
        for (int s = 0; s < 4; s++)
            t[s] = (s < sz) ? s_scale[half][s] * g_emb_new[s_nodes[half][s] * RANK + r] : 1.0f;
        float loo[4];
        loo[0] = t[1] * t[2] * t[3];
        loo[1] = t[0] * t[2] * t[3];
        loo[2] = t[0] * t[1] * t[3];
        loo[3] = t[0] * t[1] * t[2];
        float f = gf * invf;
        unsigned tb = (unsigned)e * (4u * RANK) + r;
        for (int s = 0; s < sz; s++)
            g_tee[tb + (unsigned)s * RANK] = __float2half_rn(tanhf(loo[s] * f));
    }

    {
        float sum0 = 0.f, sum1 = 0.f;
        for (int s = 0; s < sz; s++) {
            const __half2* row = (const __half2*)(g_emb_new2 + (unsigned)s_nodes[half][s] * OUTD);
            float2 v = __half22float2(row[lt]);
            sum0 += v.x;
            sum1 += v.y;
        }
        __half2* out = (__half2*)(g_esum2 + (unsigned)e * OUTD);
        out[lt] = __floats2half2_rn(fmaxf(sum0, 0.f), fmaxf(sum1, 0.f));
    }
}

// ---------------- node-major gather (unrolled x4, fp16 sources, fp32 accumulate) ----------------
__global__ __launch_bounds__(256)
void node_gather()
{
    int n = blockIdx.x;
    int tid = threadIdx.x;
    int s0 = g_offs[n], s1 = g_offs[n + 1];
    float acc0 = 0.f, acc1 = 0.f, acc2 = 0.f, acc3 = 0.f;
    float ar0 = 0.f, ar1 = 0.f, ar2 = 0.f, ar3 = 0.f;
    int j = s0;
    for (; j + 3 < s1; j += 4) {
        int cA = g_csr[j], cB = g_csr[j + 1], cC = g_csr[j + 2], cD = g_csr[j + 3];
        acc0 += __half2float(g_esum2[(unsigned)(cA >> 2) * OUTD + tid]);
        acc1 += __half2float(g_esum2[(unsigned)(cB >> 2) * OUTD + tid]);
        acc2 += __half2float(g_esum2[(unsigned)(cC >> 2) * OUTD + tid]);
        acc3 += __half2float(g_esum2[(unsigned)(cD >> 2) * OUTD + tid]);
        if (tid < RANK) {
            ar0 += __half2float(g_tee[(unsigned)cA * RANK + tid]);
            ar1 += __half2float(g_tee[(unsigned)cB * RANK + tid]);
            ar2 += __half2float(g_tee[(unsigned)cC * RANK + tid]);
            ar3 += __half2float(g_tee[(unsigned)cD * RANK + tid]);
        }
    }
    for (; j < s1; ++j) {
        int code = g_csr[j];
        acc0 += __half2float(g_esum2[(unsigned)(code >> 2) * OUTD + tid]);
        if (tid < RANK) ar0 += __half2float(g_tee[(unsigned)code * RANK + tid]);
    }
    g_nodeacc[(unsigned)n * OUTD + tid] = (acc0 + acc1) + (acc2 + acc3);
    if (tid < RANK)
        g_accRh[(unsigned)n * RANK + tid] = __float2half_rn((ar0 + ar1) + (ar2 + ar3));
}

// ---------------- launch ----------------
extern "C" void kernel_launch(void* const* d_in, const int* in_sizes, int n_in,
                              void* d_out, int out_size)
{
    const float* embedding  = (const float*)d_in[0];
    const float* global_emb = (const float*)d_in[1];
    const float* pW         = (const float*)d_in[2];
    const float* pb         = (const float*)d_in[3];
    const float* qW         = (const float*)d_in[4];
    const float* qb         = (const float*)d_in[5];
    const float* p2W1       = (const float*)d_in[6];
    const float* p2b1       = (const float*)d_in[7];
    const float* p2W2       = (const float*)d_in[8];
    const float* p2b2       = (const float*)d_in[9];
    const float* aW         = (const float*)d_in[10];
    const float* ab         = (const float*)d_in[11];
    const int*   edge_nodes = (const int*)d_in[12];
    const int*   edge_size  = (const int*)d_in[14];
    const int*   node_deg   = (const int*)d_in[15];
    const int*   inc_node   = (const int*)d_in[16];
    const int*   inc_edge   = (const int*)d_in[17];
    const int*   inc_slot   = (const int*)d_in[18];

    const int N    = in_sizes[0] / FEAT;
    const int E    = in_sizes[14];
    const int NINC = in_sizes[16];

    __half *p_embH, *p_hidden, *p_emb_new2, *p_accRh, *p_WtC, *p_Wt2, *p_WtP, *p_WtQ;
    float *p_emb_new, *p_residual, *p_nodeacc, *p_biasC, *p_biasP;
    int *p_offs, *p_cursor;
    cudaGetSymbolAddress((void**)&p_embH,     g_embH);
    cudaGetSymbolAddress((void**)&p_emb_new,  g_emb_new);
    cudaGetSymbolAddress((void**)&p_hidden,   g_hidden);
    cudaGetSymbolAddress((void**)&p_emb_new2, g_emb_new2);
    cudaGetSymbolAddress((void**)&p_residual, g_residual);
    cudaGetSymbolAddress((void**)&p_nodeacc,  g_nodeacc);
    cudaGetSymbolAddress((void**)&p_accRh,    g_accRh);
    cudaGetSymbolAddress((void**)&p_offs,     g_offs);
    cudaGetSymbolAddress((void**)&p_cursor,   g_cursor);
    cudaGetSymbolAddress((void**)&p_WtC,  g_WtC);
    cudaGetSymbolAddress((void**)&p_Wt2,  g_Wt2);
    cudaGetSymbolAddress((void**)&p_WtP,  g_WtP);
    cudaGetSymbolAddress((void**)&p_WtQ,  g_WtQ);
    cudaGetSymbolAddress((void**)&p_biasC, g_biasC);
    cudaGetSymbolAddress((void**)&p_biasP, g_biasP);

    const int SMEM128 = (3 * 128 * 20 + 3 * 128 * 20) * 4;  // 61440
    const int SMEM64  = (3 * 128 * 20 + 3 * 64  * 20) * 4;  // 46080
    cudaFuncSetAttribute(mma_gemm<128>, cudaFuncAttributeMaxDynamicSharedMemorySize, SMEM128);
    cudaFuncSetAttribute(mma_gemm<64>,  cudaFuncAttributeMaxDynamicSharedMemorySize, SMEM64);

    const int Mtiles = (N + 127) / 128;   // 235
    const int n4 = N * FEAT / 4;

    // 0: CSR offsets
    scan_offsets<<<1, 1024>>>(node_deg, p_offs, p_cursor, N);
    // 1: CSR fill
    csr_fill<<<(NINC + 255) / 256, 256>>>(inc_node, inc_edge, inc_slot, NINC);
    // 2: mega-prep
    prep_all<<<614 + (n4 + 255) / 256, 256>>>(embedding, p2W1, p2W2, aW, pW, qW,
                                              p2b1, ab, pb, n4);
    // 3 (ncu target): merged G2+G4: [hidden(h) | residual(f)] = relu(embH @ WtC^T + biasC)
    mma_gemm<128><<<dim3(NC / 128, Mtiles), 256, SMEM128>>>(
        p_embH, p_WtC, p_biasC, (float*)p_hidden, p_residual, N, NC, FEAT, 3,
        nullptr, nullptr, nullptr);
    // 4: G1 emb_new(f32) = embH @ pW^T + biasP                      [N x 64]
    mma_gemm<64><<<dim3(1, Mtiles), 256, SMEM64>>>(
        p_embH, p_WtP, p_biasP, p_emb_new, nullptr, N, RANK, FEAT, 0,
        nullptr, nullptr, nullptr);
    // 5: G3 emb_new2(h) = hidden @ p2W2 + p2b2   [N x 256], NT=128
    mma_gemm<128><<<dim3(OUTD / 128, Mtiles), 256, SMEM128>>>(
        p_hidden, p_Wt2, p2b2, (float*)p_emb_new2, nullptr, N, OUTD, HID, 4,
        nullptr, nullptr, nullptr);
    // 6: edge-level tanh(ee)(h) + relu(esum2)(h)
    edge_kernel<<<(E + 1) / 2, 256>>>(global_emb, edge_nodes, edge_size, node_deg, E);
    // 7: node-major gather
    node_gather<<<N, 256>>>();
    // 8: final fused GEMM, NT=128
    mma_gemm<128><<<dim3(OUTD / 128, Mtiles), 256, SMEM128>>>(
        p_accRh, p_WtQ, qb, (float*)d_out, nullptr, N, OUTD, RANK, 2,
        p_nodeacc, p_residual, node_deg);
}

// round 17
// speedup vs baseline: 1.1117x; 1.0540x over previous
#include <cuda_runtime.h>
#include <cuda_fp16.h>
#include <math.h>
#include <stdint.h>

// Problem constants
#define NN   30000
#define NE   60000
#define FEAT 256
#define HID  1024
#define OUTD 256
#define RANK 64
#define NC   1280   // HID + OUTD (merged G2+G4)

// ---------------- scratch (device globals) ----------------
__device__ __half g_embH    [NN * FEAT];
__device__ float  g_emb_new [NN * RANK];
__device__ __half g_hidden  [NN * HID];
__device__ __half g_emb_new2[NN * OUTD];
__device__ __half g_residualH[NN * OUTD];    // fp16
__device__ __half g_tee     [NE * 4 * RANK];
__device__ __half g_esum2   [NE * OUTD];
__device__ __half g_nodeaccH[NN * OUTD];     // fp16
__device__ __half g_accRh   [NN * RANK];
__device__ int    g_offs    [NN + 1];
__device__ int    g_cursor  [NN];
__device__ int    g_csr     [NE * 4];
// K-major fp16 weights
__device__ __half g_WtC [NC * FEAT];
__device__ __half g_Wt2 [OUTD * HID];
__device__ __half g_WtP [RANK * FEAT];
__device__ __half g_WtQ [OUTD * RANK];
__device__ float  g_biasC [NC];
__device__ float  g_biasP [RANK];

// ---------------- helpers ----------------
__device__ __forceinline__ uint32_t smem_u32(const void* p) {
    uint32_t a;
    asm("{ .reg .u64 t; cvta.to.shared.u64 t, %1; cvt.u32.u64 %0, t; }" : "=r"(a) : "l"(p));
    return a;
}
__device__ __forceinline__ uint32_t h2_as_u32(__half2 h) {
    uint32_t u;
    memcpy(&u, &h, 4);
    return u;
}
__device__ __forceinline__ void cp16(uint32_t dst, const void* src, int szbytes) {
    asm volatile("cp.async.ca.shared.global [%0], [%1], 16, %2;"
                 :: "r"(dst), "l"(src), "r"(szbytes) : "memory");
}
#define CP_COMMIT() asm volatile("cp.async.commit_group;" ::: "memory")
#define CP_WAIT(n)  asm volatile("cp.async.wait_group %0;" :: "n"(n) : "memory")

__device__ __forceinline__ void mma16n8k16(float* d, const uint32_t* a, const uint32_t* b) {
    asm volatile(
        "mma.sync.aligned.m16n8k16.row.col.f32.f16.f16.f32 "
        "{%0,%1,%2,%3}, {%4,%5,%6,%7}, {%8,%9}, {%0,%1,%2,%3};"
        : "+f"(d[0]), "+f"(d[1]), "+f"(d[2]), "+f"(d[3])
        : "r"(a[0]), "r"(a[1]), "r"(a[2]), "r"(a[3]), "r"(b[0]), "r"(b[1]));
}
__device__ __forceinline__ void ldsm_x4(uint32_t* r, uint32_t addr) {
    asm volatile("ldmatrix.sync.aligned.m8n8.x4.shared.b16 {%0,%1,%2,%3}, [%4];"
        : "=r"(r[0]), "=r"(r[1]), "=r"(r[2]), "=r"(r[3]) : "r"(addr));
}

// ---------------- mega-prep (+ embedded CSR offset scan in last block) ----------------
// blocks [0,608): transposes; [608,614): biases; [614,614+nEmb): emb fp16; last: scan
__global__ void prep_all(const float* __restrict__ emb,
                         const float* __restrict__ p2W1, const float* __restrict__ p2W2,
                         const float* __restrict__ aW,   const float* __restrict__ pW,
                         const float* __restrict__ qW,
                         const float* __restrict__ p2b1, const float* __restrict__ ab_,
                         const float* __restrict__ pb_,
                         const int* __restrict__ deg, int n4, int nEmb)
{
    __shared__ float t[32][33];
    __shared__ int wsum[32];
    const int bx = blockIdx.x;
    const int tid = threadIdx.x;
    if (bx < 608) {
        const float* W; __half* Wt; int K, N, t0;
        if      (bx < 256) { W = p2W1; Wt = g_WtC;              K = FEAT; N = HID;  t0 = 0;   }
        else if (bx < 512) { W = p2W2; Wt = g_Wt2;              K = HID;  N = OUTD; t0 = 256; }
        else if (bx < 576) { W = aW;   Wt = g_WtC + HID * FEAT; K = FEAT; N = OUTD; t0 = 512; }
        else if (bx < 592) { W = pW;   Wt = g_WtP;              K = FEAT; N = RANK; t0 = 576; }
        else               { W = qW;   Wt = g_WtQ;              K = RANK; N = OUTD; t0 = 592; }
        int tt = bx - t0;
        int tiles_n = N >> 5;
        int n0 = (tt % tiles_n) * 32, k0 = (tt / tiles_n) * 32;
        int tx = tid & 31, ty = tid >> 5;
        for (int i = ty; i < 32; i += 8)
            t[i][tx] = W[(k0 + i) * N + n0 + tx];
        __syncthreads();
        for (int i = ty; i < 32; i += 8)
            Wt[(n0 + i) * K + k0 + tx] = __float2half_rn(t[tx][i]);
    } else if (bx < 614) {
        int i = (bx - 608) * 256 + tid;
        if      (i < HID)        g_biasC[i] = p2b1[i] + p2W1[FEAT * HID + i];
        else if (i < HID + OUTD) g_biasC[i] = ab_[i - HID] + aW[FEAT * OUTD + (i - HID)];
        else if (i < HID + OUTD + RANK) g_biasP[i - HID - OUTD] = pb_[i - HID - OUTD] + pW[FEAT * RANK + (i - HID - OUTD)];
    } else if (bx < 614 + nEmb) {
        int i = (bx - 614) * 256 + tid;
        if (i < n4) {
            float4 v = ((const float4*)emb)[i];
            uint2 o;
            o.x = h2_as_u32(__floats2half2_rn(v.x, v.y));
            o.y = h2_as_u32(__floats2half2_rn(v.z, v.w));
            ((uint2*)g_embH)[i] = o;
        }
    } else {
        // CSR offset scan: 256 threads, 120 elems each (int4-aligned)
        const int Nn = n4 >> 6;           // 30000
        const int CE = 120;
        const int start = tid * CE;
        int local = 0;
        for (int j = 0; j < CE; j += 4) {
            int i = start + j;
            if (i + 3 < Nn) {
                int4 v = *(const int4*)(deg + i);
                local += v.x + v.y + v.z + v.w;
            } else {
                #pragma unroll
                for (int k2 = 0; k2 < 4; k2++) if (i + k2 < Nn) local += deg[i + k2];
            }
        }
        int lane = tid & 31, w = tid >> 5;
        int x = local;
        #pragma unroll
        for (int o = 1; o < 32; o <<= 1) { int y = __shfl_up_sync(~0u, x, o); if (lane >= o) x += y; }
        if (lane == 31) wsum[w] = x;
        __syncthreads();
        if (w == 0) {
            int s = (lane < 8) ? wsum[lane] : 0;
            #pragma unroll
            for (int o = 1; o < 32; o <<= 1) { int y = __shfl_up_sync(~0u, s, o); if (lane >= o) s += y; }
            if (lane < 8) wsum[lane] = s;
        }
        __syncthreads();
        int base = x - local + (w > 0 ? wsum[w - 1] : 0);
        int run = base;
        for (int j = 0; j < CE; j++) {
            int i = start + j;
            if (i < Nn) { g_offs[i] = run; g_cursor[i] = 0; run += deg[i]; }
        }
        if (tid == (Nn - 1) / CE) g_offs[Nn] = run;
    }
}

__global__ void csr_fill(const int* __restrict__ inc_node, const int* __restrict__ inc_edge,
                         const int* __restrict__ inc_slot, int NINC)
{
    int i = blockIdx.x * blockDim.x + threadIdx.x;
    if (i < NINC) {
        int n = inc_node[i];
        int p = atomicAdd(&g_cursor[n], 1);
        g_csr[g_offs[n] + p] = (inc_edge[i] << 2) | inc_slot[i];
    }
}

// ---------------- fp16 tensor-core GEMM (m16n8k16 + ldmatrix + 3-stage pipeline) ----------------
// mode 0: C(f32) = acc + bias
// mode 2: C(f32) = relu((acc + addSrcH)/deg + bias) + residH   (half aux inputs)
// mode 3: col<HID -> relu -> half2 C (stride HID); else relu -> half2 C2 (stride OUTD)
// mode 4: C = half2(acc + bias), stride N (fp16 output, no relu)
template<int NT>
__global__ __launch_bounds__(256, 2)
void mma_gemm(const __half* __restrict__ A, const __half* __restrict__ Bt,
              const float* __restrict__ bias,
              float* __restrict__ C, float* __restrict__ C2,
              int M, int N, int K, int mode,
              const __half* __restrict__ addSrcH, const __half* __restrict__ residH,
              const int* __restrict__ degv)
{
    constexpr int STW = 20;
    constexpr int NTILES = NT / 16;
    extern __shared__ uint32_t dyn32[];
    uint32_t* Asm = dyn32;                   // 3 bufs x 128 x STW words
    uint32_t* Bsm = dyn32 + 3 * 128 * STW;   // 3 bufs x NT x STW words

    const int tid  = threadIdx.x;
    const int wid  = tid >> 5;
    const int lane = tid & 31;
    const int grp  = lane >> 2;
    const int tig  = lane & 3;
    const int warpM = (wid & 3) * 32;
    const int warpN = (wid >> 2) * (NT / 2);
    const int rowBase = blockIdx.y * 128;
    const int colBase = blockIdx.x * NT;

    float acc[2][NTILES][4];
    #pragma unroll
    for (int mt = 0; mt < 2; mt++)
        #pragma unroll
        for (int nt = 0; nt < NTILES; nt++)
            #pragma unroll
            for (int i = 0; i < 4; i++) acc[mt][nt][i] = 0.f;

    const uint32_t asm_base = smem_u32(Asm);
    const uint32_t bsm_base = smem_u32(Bsm);

    const int lrow8 = lane & 7;
    const int a_row_off = lrow8 + (((lane >> 3) & 1) << 3);
    const int a_col_off = ((lane >> 4) << 2);
    const int b_row_off = lrow8 + ((lane >> 4) << 3);
    const int b_col_off = (((lane >> 3) & 1) << 2);

    auto loadChunk = [&](int c, int buf) {
        #pragma unroll
        for (int i = 0; i < 2; i++) {
            int idx = tid + (i << 8);
            int r = idx >> 2, seg = idx & 3;
            int gr = rowBase + r;
            const __half* src = A + (size_t)gr * K + (c << 5) + (seg << 3);
            uint32_t dst = asm_base + (buf * 128 * STW + r * STW + (seg << 2)) * 4;
            cp16(dst, src, gr < M ? 16 : 0);
        }
        #pragma unroll
        for (int i = 0; i < NT / 64; i++) {
            int idx = tid + (i << 8);
            int r = idx >> 2, seg = idx & 3;
            const __half* src = Bt + (size_t)(colBase + r) * K + (c << 5) + (seg << 3);
            uint32_t dst = bsm_base + (buf * NT * STW + r * STW + (seg << 2)) * 4;
            cp16(dst, src, 16);
        }
        CP_COMMIT();
    };

    const int nch = K >> 5;
    loadChunk(0, 0);
    loadChunk(1, 1);

    int buf = 0;
    for (int c = 0; c < nch; ++c) {
        if (c + 1 < nch) { CP_WAIT(1); }
        else             { CP_WAIT(0); }
        __syncthreads();
        if (c + 2 < nch) {
            int nb = buf + 2; if (nb >= 3) nb -= 3;
            loadChunk(c + 2, nb);
        }

        const uint32_t abase = asm_base + (buf * 128 * STW) * 4;
        const uint32_t bbase = bsm_base + (buf * NT * STW) * 4;
        #pragma unroll
        for (int ks = 0; ks < 2; ++ks) {
            const int kw = ks << 3;
            uint32_t afr[2][4];
            #pragma unroll
            for (int mt = 0; mt < 2; mt++) {
                uint32_t ad = abase +
                    ((warpM + mt * 16 + a_row_off) * STW + kw + a_col_off) * 4;
                ldsm_x4(afr[mt], ad);
            }
            uint32_t bfr[NTILES][2];
            #pragma unroll
            for (int p = 0; p < NTILES / 2; p++) {
                uint32_t bd = bbase +
                    ((warpN + p * 16 + b_row_off) * STW + kw + b_col_off) * 4;
                uint32_t r4[4];
                ldsm_x4(r4, bd);
                bfr[2 * p][0] = r4[0]; bfr[2 * p][1] = r4[1];
                bfr[2 * p + 1][0] = r4[2]; bfr[2 * p + 1][1] = r4[3];
            }
            #pragma unroll
            for (int mt = 0; mt < 2; mt++)
                #pragma unroll
                for (int nt = 0; nt < NTILES; nt++)
                    mma16n8k16(acc[mt][nt], afr[mt], bfr[nt]);
        }
        buf++; if (buf >= 3) buf = 0;
    }

    #pragma unroll
    for (int mt = 0; mt < 2; mt++) {
        #pragma unroll
        for (int nt = 0; nt < NTILES; nt++) {
            int col = colBase + warpN + nt * 8 + (tig << 1);
            float b0 = bias[col], b1 = bias[col + 1];
            #pragma unroll
            for (int h = 0; h < 2; h++) {
                int row = rowBase + warpM + mt * 16 + grp + h * 8;
                if (row >= M) continue;
                float v0 = acc[mt][nt][2 * h];
                float v1 = acc[mt][nt][2 * h + 1];
                if (mode == 3) {
                    v0 = fmaxf(v0 + b0, 0.f); v1 = fmaxf(v1 + b1, 0.f);
                    if (col < HID) {
                        ((uint32_t*)C)[(size_t)row * (HID / 2) + (col >> 1)] =
                            h2_as_u32(__floats2half2_rn(v0, v1));
                    } else {
                        ((uint32_t*)C2)[(size_t)row * (OUTD / 2) + ((col - HID) >> 1)] =
                            h2_as_u32(__floats2half2_rn(v0, v1));
                    }
                } else if (mode == 4) {
                    ((uint32_t*)C)[(size_t)row * (N / 2) + (col >> 1)] =
                        h2_as_u32(__floats2half2_rn(v0 + b0, v1 + b1));
                } else if (mode == 2) {
                    float rd = 1.0f / (float)degv[row];
                    size_t base = (size_t)row * N + col;
                    v0 = fmaxf((v0 + __half2float(addSrcH[base]))     * rd + b0, 0.f)
                         + __half2float(residH[base]);
                    v1 = fmaxf((v1 + __half2float(addSrcH[base + 1])) * rd + b1, 0.f)
                         + __half2float(residH[base + 1]);
                    *(float2*)(C + base) = make_float2(v0, v1);
                } else {
                    *(float2*)(C + (size_t)row * N + col) = make_float2(v0 + b0, v1 + b1);
                }
            }
        }
    }
}

// ---------------- edge kernel: 2 edges per block ----------------
__global__ __launch_bounds__(256)
void edge_kernel(const float* __restrict__ global_emb,
                 const int* __restrict__ edge_nodes,
                 const int* __restrict__ edge_size,
                 const int* __restrict__ node_degree,
                 int E)
{
    __shared__ int   s_nodes[2][4];
    __shared__ float s_scale[2][4];
    __shared__ int   s_size[2];

    const int half = threadIdx.x >> 7;
    const int lt   = threadIdx.x & 127;
    const int e    = blockIdx.x * 2 + half;
    const bool active = (e < E);

    if (active && lt < 4) {
        int sz = edge_size[e];
        if (lt == 0) s_size[half] = sz;
        int n = edge_nodes[e * 4 + lt];
        s_nodes[half][lt] = n;
        float a = (sz == 1) ? 1.0f : (sz <= 3 ? (1.0f / 3.0f) : 0.25f);
        s_scale[half][lt] = __powf((float)node_degree[n], a);
    }
    __syncthreads();
    if (!active) return;

    const int sz = s_size[half];
    const int k = 4 - sz;
    const float invf = (sz == 3) ? 0.5f : (sz == 4 ? (1.0f / 6.0f) : 1.0f);

    if (lt < RANK) {
        const int r = lt;
        float g = global_emb[r];
        float gf = (k == 0) ? 1.0f : (k == 1 ? g : g * g);
        float t[4];
        #pragma unroll
        for (int s = 0; s < 4; s++)
            t[s] = (s < sz) ? s_scale[half][s] * g_emb_new[s_nodes[half][s] * RANK + r] : 1.0f;
        float loo[4];
        loo[0] = t[1] * t[2] * t[3];
        loo[1] = t[0] * t[2] * t[3];
        loo[2] = t[0] * t[1] * t[3];
        loo[3] = t[0] * t[1] * t[2];
        float f = gf * invf;
        unsigned tb = (unsigned)e * (4u * RANK) + r;
        for (int s = 0; s < sz; s++)
            g_tee[tb + (unsigned)s * RANK] = __float2half_rn(tanhf(loo[s] * f));
    }

    {
        float sum0 = 0.f, sum1 = 0.f;
        for (int s = 0; s < sz; s++) {
            const __half2* row = (const __half2*)(g_emb_new2 + (unsigned)s_nodes[half][s] * OUTD);
            float2 v = __half22float2(row[lt]);
            sum0 += v.x;
            sum1 += v.y;
        }
        __half2* out = (__half2*)(g_esum2 + (unsigned)e * OUTD);
        out[lt] = __floats2half2_rn(fmaxf(sum0, 0.f), fmaxf(sum1, 0.f));
    }
}

// ---------------- node-major gather (unrolled x4, fp16 in/out, fp32 accumulate) ----------------
__global__ __launch_bounds__(256)
void node_gather()
{
    int n = blockIdx.x;
    int tid = threadIdx.x;
    int s0 = g_offs[n], s1 = g_offs[n + 1];
    float acc0 = 0.f, acc1 = 0.f, acc2 = 0.f, acc3 = 0.f;
    float ar0 = 0.f, ar1 = 0.f, ar2 = 0.f, ar3 = 0.f;
    int j = s0;
    for (; j + 3 < s1; j += 4) {
        int cA = g_csr[j], cB = g_csr[j + 1], cC = g_csr[j + 2], cD = g_csr[j + 3];
        acc0 += __half2float(g_esum2[(unsigned)(cA >> 2) * OUTD + tid]);
        acc1 += __half2float(g_esum2[(unsigned)(cB >> 2) * OUTD + tid]);
        acc2 += __half2float(g_esum2[(unsigned)(cC >> 2) * OUTD + tid]);
        acc3 += __half2float(g_esum2[(unsigned)(cD >> 2) * OUTD + tid]);
        if (tid < RANK) {
            ar0 += __half2float(g_tee[(unsigned)cA * RANK + tid]);
            ar1 += __half2float(g_tee[(unsigned)cB * RANK + tid]);
            ar2 += __half2float(g_tee[(unsigned)cC * RANK + tid]);
            ar3 += __half2float(g_tee[(unsigned)cD * RANK + tid]);
        }
    }
    for (; j < s1; ++j) {
        int code = g_csr[j];
        acc0 += __half2float(g_esum2[(unsigned)(code >> 2) * OUTD + tid]);
        if (tid < RANK) ar0 += __half2float(g_tee[(unsigned)code * RANK + tid]);
    }
    g_nodeaccH[(unsigned)n * OUTD + tid] = __float2half_rn((acc0 + acc1) + (acc2 + acc3));
    if (tid < RANK)
        g_accRh[(unsigned)n * RANK + tid] = __float2half_rn((ar0 + ar1) + (ar2 + ar3));
}

// ---------------- launch ----------------
extern "C" void kernel_launch(void* const* d_in, const int* in_sizes, int n_in,
                              void* d_out, int out_size)
{
    const float* embedding  = (const float*)d_in[0];
    const float* global_emb = (const float*)d_in[1];
    const float* pW         = (const float*)d_in[2];
    const float* pb         = (const float*)d_in[3];
    const float* qW         = (const float*)d_in[4];
    const float* qb         = (const float*)d_in[5];
    const float* p2W1       = (const float*)d_in[6];
    const float* p2b1       = (const float*)d_in[7];
    const float* p2W2       = (const float*)d_in[8];
    const float* p2b2       = (const float*)d_in[9];
    const float* aW         = (const float*)d_in[10];
    const float* ab         = (const float*)d_in[11];
    const int*   edge_nodes = (const int*)d_in[12];
    const int*   edge_size  = (const int*)d_in[14];
    const int*   node_deg   = (const int*)d_in[15];
    const int*   inc_node   = (const int*)d_in[16];
    const int*   inc_edge   = (const int*)d_in[17];
    const int*   inc_slot   = (const int*)d_in[18];

    const int N    = in_sizes[0] / FEAT;
    const int E    = in_sizes[14];
    const int NINC = in_sizes[16];

    __half *p_embH, *p_hidden, *p_emb_new2, *p_residualH, *p_nodeaccH, *p_accRh;
    __half *p_WtC, *p_Wt2, *p_WtP, *p_WtQ;
    float *p_emb_new, *p_biasC, *p_biasP;
    cudaGetSymbolAddress((void**)&p_embH,      g_embH);
    cudaGetSymbolAddress((void**)&p_emb_new,   g_emb_new);
    cudaGetSymbolAddress((void**)&p_hidden,    g_hidden);
    cudaGetSymbolAddress((void**)&p_emb_new2,  g_emb_new2);
    cudaGetSymbolAddress((void**)&p_residualH, g_residualH);
    cudaGetSymbolAddress((void**)&p_nodeaccH,  g_nodeaccH);
    cudaGetSymbolAddress((void**)&p_accRh,     g_accRh);
    cudaGetSymbolAddress((void**)&p_WtC,  g_WtC);
    cudaGetSymbolAddress((void**)&p_Wt2,  g_Wt2);
    cudaGetSymbolAddress((void**)&p_WtP,  g_WtP);
    cudaGetSymbolAddress((void**)&p_WtQ,  g_WtQ);
    cudaGetSymbolAddress((void**)&p_biasC, g_biasC);
    cudaGetSymbolAddress((void**)&p_biasP, g_biasP);

    const int SMEM128 = (3 * 128 * 20 + 3 * 128 * 20) * 4;  // 61440
    const int SMEM64  = (3 * 128 * 20 + 3 * 64  * 20) * 4;  // 46080
    cudaFuncSetAttribute(mma_gemm<128>, cudaFuncAttributeMaxDynamicSharedMemorySize, SMEM128);
    cudaFuncSetAttribute(mma_gemm<64>,  cudaFuncAttributeMaxDynamicSharedMemorySize, SMEM64);

    const int Mtiles = (N + 127) / 128;   // 235
    const int n4 = N * FEAT / 4;
    const int nEmb = (n4 + 255) / 256;

    // 0: mega-prep (transposes + biases + emb fp16 + CSR offset scan)
    prep_all<<<614 + nEmb + 1, 256>>>(embedding, p2W1, p2W2, aW, pW, qW,
                                      p2b1, ab, pb, node_deg, n4, nEmb);
    // 1: CSR fill
    csr_fill<<<(NINC + 255) / 256, 256>>>(inc_node, inc_edge, inc_slot, NINC);
    // 2: G1 emb_new(f32) = embH @ pW^T + biasP                      [N x 64]
    mma_gemm<64><<<dim3(1, Mtiles), 256, SMEM64>>>(
        p_embH, p_WtP, p_biasP, p_emb_new, nullptr, N, RANK, FEAT, 0,
        nullptr, nullptr, nullptr);
    // 3 (ncu target): merged G2+G4: [hidden(h) | residual(h)] = relu(embH @ WtC^T + biasC)
    mma_gemm<128><<<dim3(NC / 128, Mtiles), 256, SMEM128>>>(
        p_embH, p_WtC, p_biasC, (float*)p_hidden, (float*)p_residualH, N, NC, FEAT, 3,
        nullptr, nullptr, nullptr);
    // 4: G3 emb_new2(h) = hidden @ p2W2 + p2b2   [N x 256]
    mma_gemm<128><<<dim3(OUTD / 128, Mtiles), 256, SMEM128>>>(
        p_hidden, p_Wt2, p2b2, (float*)p_emb_new2, nullptr, N, OUTD, HID, 4,
        nullptr, nullptr, nullptr);
    // 5: edge-level tanh(ee)(h) + relu(esum2)(h)
    edge_kernel<<<(E + 1) / 2, 256>>>(global_emb, edge_nodes, edge_size, node_deg, E);
    // 6: node-major gather
    node_gather<<<N, 256>>>();
    // 7: final fused GEMM: out = relu((accRh@qW^T + nodeaccH)/deg + qb) + residualH
    mma_gemm<128><<<dim3(OUTD / 128, Mtiles), 256, SMEM128>>>(
        p_accRh, p_WtQ, qb, (float*)d_out, nullptr, N, OUTD, RANK, 2,
        p_nodeaccH, p_residualH, node_deg);
}